// round 14
// baseline (speedup 1.0000x reference)
#include <cuda_runtime.h>

// Davies-Bouldin index, K=100 clusters, D=64 dims, N=2M fp32 points.
//
// 3 launches (graph-capturable, allocation-free):
//   dbi_init : parallel zero of accumulators + dtype sniff (block 0):
//              JAX x64-off silently makes `clustering` int32.
//   dbi_pass1: streaming pass, R8-proven phases/gather. Each block now
//              processes 2 tiles of 2048 points (tile = bid, bid+grid) so
//              co-resident blocks desynchronize and one block's binning
//              phases (hist/scan/scatter; DRAM-idle) overlap other blocks'
//              gather traffic -- kills the lockstep binning bubble of the
//              single-tile version. Per tile: counting-sort by cluster id
//              in smem (warp-parallel scan), then each warp reduces whole
//              clusters in registers (lane l owns dims 2l,2l+1 -> one
//              coalesced 256B row per warp-load, warp-uniform s_order
//              index keeps addresses on the uniform datapath), flush 66
//              floats per (tile,cluster) via global atomicAdd.
//   dbi_epi  : multi-block epilogue (R8-proven, ~free): every block
//              recomputes Ai/Si from g_acc into smem via
//              sum||x-A||^2 = S2 - 2*A.Sx + n*||A||^2 (no 2nd data pass);
//              block i reduces max_j (Si+Sj)/||Ai-Aj||, atomicAdd /K.
//              (The single-block variant tried in R11/R12 cost ~68us of
//              one-SM serial smem traffic -- reverted.)

#define KCLUS 100
#define DFEAT 64
#define ACCW  66            // 64 dims + sumsq + count
#define TILE  2048
#define TPB   256

__device__ float g_acc[KCLUS * ACCW];
__device__ int   g_is64;

// Sniff: view labels as int32 words. int64 (LE, values 0..99) => all odd
// words are 0. int32 => odd-word slots hold uniform cluster ids;
// P(64 samples all zero) ~ 1e-128. Samples stay inside the int32 extent.
__global__ void dbi_init(const int* __restrict__ cl32, int n, float* out) {
    int i = blockIdx.x * blockDim.x + threadIdx.x;
    if (i < KCLUS * ACCW) g_acc[i] = 0.0f;

    if (blockIdx.x == 0) {
        __shared__ int s_flag;
        if (threadIdx.x == 0) s_flag = 0;
        __syncthreads();
        if (threadIdx.x < 64) {
            int step = n / 130;
            if (cl32[2 * (threadIdx.x * step) + 1] != 0) atomicOr(&s_flag, 1);
        }
        __syncthreads();
        if (threadIdx.x == 0) { g_is64 = s_flag ? 0 : 1; out[0] = 0.0f; }
    }
}

__global__ __launch_bounds__(TPB) void dbi_pass1(const float* __restrict__ X,
                                                 const void* __restrict__ cl_raw,
                                                 int n, int ntiles) {
    __shared__ unsigned char  s_cid[TILE];
    __shared__ unsigned short s_order[TILE];
    __shared__ int s_hist[KCLUS];
    __shared__ int s_start[KCLUS + 1];
    __shared__ int s_cursor[KCLUS];
    __shared__ int s_wsum[4];

    const int t    = threadIdx.x;
    const int lane = t & 31;
    const int wid  = t >> 5;
    const int is64 = g_is64;

    for (int tile = blockIdx.x; tile < ntiles; tile += gridDim.x) {
        const int base = tile * TILE;
        const int cnt  = min(TILE, n - base);

        // zero hist (touches only s_hist; safe vs. previous gather which
        // reads s_start/s_order). The barrier below then fences the whole
        // previous iteration before s_cid/s_order are rewritten.
        for (int i = t; i < KCLUS; i += TPB) s_hist[i] = 0;
        __syncthreads();

        // histogram + stash cluster ids (coalesced; uniform dtype branch)
        if (is64) {
            const long long* cl = (const long long*)cl_raw;
            for (int i = t; i < cnt; i += TPB) {
                int c = (int)cl[base + i];
                s_cid[i] = (unsigned char)c;
                atomicAdd(&s_hist[c], 1);
            }
        } else {
            const int* cl = (const int*)cl_raw;
            for (int i = t; i < cnt; i += TPB) {
                int c = cl[base + i];
                s_cid[i] = (unsigned char)c;
                atomicAdd(&s_hist[c], 1);
            }
        }
        __syncthreads();

        // warp-parallel exclusive prefix scan over 100 bins (warps 0-3)
        int incl = 0;
        if (t < 128) {
            incl = (t < KCLUS) ? s_hist[t] : 0;
            #pragma unroll
            for (int o = 1; o < 32; o <<= 1) {
                int u = __shfl_up_sync(0xffffffffu, incl, o);
                if (lane >= o) incl += u;
            }
            if (lane == 31) s_wsum[wid] = incl;
        }
        __syncthreads();
        if (t == 0) {
            int a = 0;
            #pragma unroll
            for (int w = 0; w < 4; w++) { int x = s_wsum[w]; s_wsum[w] = a; a += x; }
            s_start[KCLUS] = a;
        }
        __syncthreads();
        if (t < KCLUS) {
            int excl = incl - s_hist[t] + s_wsum[wid];
            s_start[t]  = excl;
            s_cursor[t] = excl;
        }
        __syncthreads();

        // scatter local indices into cluster-contiguous order
        for (int i = t; i < cnt; i += TPB) {
            int pos = atomicAdd(&s_cursor[s_cid[i]], 1);
            s_order[pos] = (unsigned short)i;
        }
        __syncthreads();

        // each warp reduces whole clusters in registers: lane l owns dims
        // 2l,2l+1 (warp-uniform s_order index -> uniform-datapath addresses)
        const int lo2 = lane << 1;
        for (int c = wid; c < KCLUS; c += (TPB >> 5)) {
            const int s = s_start[c];
            const int e = s_start[c + 1];
            const int m = e - s;
            if (m == 0) continue;

            float a0 = 0.f, a1 = 0.f, sq = 0.f;
            int j = s;
            // unroll x8: 8 independent 256B row loads in flight per warp
            for (; j + 8 <= e; j += 8) {
                float2 v0 = *(const float2*)(X + (((size_t)(base + s_order[j + 0])) << 6) + lo2);
                float2 v1 = *(const float2*)(X + (((size_t)(base + s_order[j + 1])) << 6) + lo2);
                float2 v2 = *(const float2*)(X + (((size_t)(base + s_order[j + 2])) << 6) + lo2);
                float2 v3 = *(const float2*)(X + (((size_t)(base + s_order[j + 3])) << 6) + lo2);
                float2 v4 = *(const float2*)(X + (((size_t)(base + s_order[j + 4])) << 6) + lo2);
                float2 v5 = *(const float2*)(X + (((size_t)(base + s_order[j + 5])) << 6) + lo2);
                float2 v6 = *(const float2*)(X + (((size_t)(base + s_order[j + 6])) << 6) + lo2);
                float2 v7 = *(const float2*)(X + (((size_t)(base + s_order[j + 7])) << 6) + lo2);
                a0 += ((v0.x + v1.x) + (v2.x + v3.x)) + ((v4.x + v5.x) + (v6.x + v7.x));
                a1 += ((v0.y + v1.y) + (v2.y + v3.y)) + ((v4.y + v5.y) + (v6.y + v7.y));
                sq += (v0.x * v0.x + v0.y * v0.y) + (v1.x * v1.x + v1.y * v1.y)
                    + (v2.x * v2.x + v2.y * v2.y) + (v3.x * v3.x + v3.y * v3.y)
                    + (v4.x * v4.x + v4.y * v4.y) + (v5.x * v5.x + v5.y * v5.y)
                    + (v6.x * v6.x + v6.y * v6.y) + (v7.x * v7.x + v7.y * v7.y);
            }
            for (; j < e; j++) {
                float2 v0 = *(const float2*)(X + (((size_t)(base + s_order[j])) << 6) + lo2);
                a0 += v0.x;
                a1 += v0.y;
                sq += v0.x * v0.x + v0.y * v0.y;
            }

            atomicAdd(&g_acc[c * ACCW + lo2 + 0], a0);
            atomicAdd(&g_acc[c * ACCW + lo2 + 1], a1);
            #pragma unroll
            for (int o = 16; o; o >>= 1) sq += __shfl_xor_sync(0xffffffffu, sq, o);
            if (lane == 0) {
                atomicAdd(&g_acc[c * ACCW + 64], sq);
                atomicAdd(&g_acc[c * ACCW + 65], (float)m);
            }
        }
    }
}

// Multi-block epilogue (R8-proven): every block recomputes Ai/Si (26KB L2
// reads, cheap), transposed smem layout [d*K+k] => conflict-free; block i
// reduces its row max over j with 128 threads (<=1 j per thread).
__global__ void dbi_epi(float* out) {
    __shared__ float sA[DFEAT * KCLUS];
    __shared__ float sS[KCLUS];
    __shared__ float wmax[4];
    const int t = threadIdx.x;

    if (t < KCLUS) {
        float nk  = g_acc[t * ACCW + 65];
        float inv = 1.0f / (1.0f + nk);
        float dot = 0.f, nrm = 0.f;
        #pragma unroll
        for (int d = 0; d < DFEAT; d++) {
            float sx = g_acc[t * ACCW + d];
            float a  = (0.001f + sx) * inv;
            sA[d * KCLUS + t] = a;
            dot += a * sx;
            nrm += a * a;
        }
        float ssq = g_acc[t * ACCW + 64] - 2.0f * dot + nk * nrm;
        sS[t] = sqrtf((0.001f + ssq) * inv);
    }
    __syncthreads();

    const int i  = blockIdx.x;
    const float si = sS[i];
    float best = 0.f;
    for (int j = t; j < KCLUS; j += 128) {
        if (j == i) continue;
        float ss = 0.f;
        #pragma unroll
        for (int d = 0; d < DFEAT; d++) {
            float df = sA[d * KCLUS + i] - sA[d * KCLUS + j];
            ss += df * df;
        }
        best = fmaxf(best, (si + sS[j]) / sqrtf(ss));
    }
    #pragma unroll
    for (int o = 16; o; o >>= 1) best = fmaxf(best, __shfl_xor_sync(0xffffffffu, best, o));
    if ((t & 31) == 0) wmax[t >> 5] = best;
    __syncthreads();
    if (t == 0) {
        float b = fmaxf(fmaxf(wmax[0], wmax[1]), fmaxf(wmax[2], wmax[3]));
        atomicAdd(out, b * (1.0f / (float)KCLUS));
    }
}

extern "C" void kernel_launch(void* const* d_in, const int* in_sizes, int n_in,
                              void* d_out, int out_size) {
    const float* X  = (const float*)d_in[0];
    const void*  cl = d_in[1];
    float* out = (float*)d_out;

    int n = (n_in >= 2) ? in_sizes[1] : (in_sizes[0] / DFEAT);
    int ntiles = (n + TILE - 1) / TILE;
    int grid   = (ntiles + 1) / 2;     // 2 tiles per block, balanced

    dbi_init<<<(KCLUS * ACCW + 255) / 256, 256>>>((const int*)cl, n, out);
    dbi_pass1<<<grid, TPB>>>(X, cl, n, ntiles);
    dbi_epi<<<KCLUS, 128>>>(out);
    (void)out_size;
}

// round 15
// speedup vs baseline: 1.3789x; 1.3789x over previous
#include <cuda_runtime.h>

// Davies-Bouldin index, K=100 clusters, D=64 dims, N=2M fp32 points.
//
// 3 launches (graph-capturable, allocation-free):
//   dbi_init : parallel zero of accumulators + dtype sniff (block 0):
//              JAX x64-off silently makes `clustering` int32.
//   dbi_pass1: streaming pass, R8-proven phases/gather; scaled UP to
//              TILE=8192 / TPB=512 / grid=245 (one wave, 2 CTAs/SM forced
//              via __launch_bounds__). Ledger: TILE=2048 cost +30us vs
//              TILE=4096 (2x flush atomics + 2x binning phases) -- so go
//              the other way: halve atomics (1.6M REDG), halve phase
//              count, halve tail fraction, same 26 gather-warps/SM.
//              Per tile: counting-sort by cluster id in smem (warp-parallel
//              scan over 100 bins), then each warp reduces whole clusters
//              in registers (lane l owns dims 2l,2l+1 -> one coalesced
//              256B row per warp-load; warp-uniform s_order index keeps
//              addresses on the uniform datapath), flush 66 floats per
//              (tile,cluster) via global atomicAdd.
//   dbi_epi  : multi-block epilogue (R8-proven, ~free; the single-block
//              variant measured ~40us of one-SM serial smem traffic).
//              Ai/Si from g_acc via sum||x-A||^2 = S2 - 2*A.Sx + n*||A||^2
//              (no 2nd data pass); block i reduces max_j (Si+Sj)/||Ai-Aj||,
//              atomicAdd /K.

#define KCLUS 100
#define DFEAT 64
#define ACCW  66            // 64 dims + sumsq + count
#define TILE  8192
#define TPB   512

__device__ float g_acc[KCLUS * ACCW];
__device__ int   g_is64;

// Sniff: view labels as int32 words. int64 (LE, values 0..99) => all odd
// words are 0. int32 => odd-word slots hold uniform cluster ids;
// P(64 samples all zero) ~ 1e-128. Samples stay inside the int32 extent.
__global__ void dbi_init(const int* __restrict__ cl32, int n, float* out) {
    int i = blockIdx.x * blockDim.x + threadIdx.x;
    if (i < KCLUS * ACCW) g_acc[i] = 0.0f;

    if (blockIdx.x == 0) {
        __shared__ int s_flag;
        if (threadIdx.x == 0) s_flag = 0;
        __syncthreads();
        if (threadIdx.x < 64) {
            int step = n / 130;
            if (cl32[2 * (threadIdx.x * step) + 1] != 0) atomicOr(&s_flag, 1);
        }
        __syncthreads();
        if (threadIdx.x == 0) { g_is64 = s_flag ? 0 : 1; out[0] = 0.0f; }
    }
}

__global__ __launch_bounds__(TPB, 2) void dbi_pass1(const float* __restrict__ X,
                                                    const void* __restrict__ cl_raw,
                                                    int n) {
    __shared__ unsigned char  s_cid[TILE];
    __shared__ unsigned short s_order[TILE];
    __shared__ int s_hist[KCLUS];
    __shared__ int s_start[KCLUS + 1];
    __shared__ int s_cursor[KCLUS];
    __shared__ int s_wsum[4];

    const int base = blockIdx.x * TILE;
    const int cnt  = min(TILE, n - base);
    const int t    = threadIdx.x;
    const int lane = t & 31;
    const int wid  = t >> 5;

    for (int i = t; i < KCLUS; i += TPB) s_hist[i] = 0;
    __syncthreads();

    // histogram + stash cluster ids (coalesced; uniform dtype branch)
    if (g_is64) {
        const long long* cl = (const long long*)cl_raw;
        for (int i = t; i < cnt; i += TPB) {
            int c = (int)cl[base + i];
            s_cid[i] = (unsigned char)c;
            atomicAdd(&s_hist[c], 1);
        }
    } else {
        const int* cl = (const int*)cl_raw;
        for (int i = t; i < cnt; i += TPB) {
            int c = cl[base + i];
            s_cid[i] = (unsigned char)c;
            atomicAdd(&s_hist[c], 1);
        }
    }
    __syncthreads();

    // warp-parallel exclusive prefix scan over 100 bins (warps 0-3)
    int incl = 0;
    if (t < 128) {
        incl = (t < KCLUS) ? s_hist[t] : 0;
        #pragma unroll
        for (int o = 1; o < 32; o <<= 1) {
            int u = __shfl_up_sync(0xffffffffu, incl, o);
            if (lane >= o) incl += u;
        }
        if (lane == 31) s_wsum[wid] = incl;
    }
    __syncthreads();
    if (t == 0) {
        int a = 0;
        #pragma unroll
        for (int w = 0; w < 4; w++) { int x = s_wsum[w]; s_wsum[w] = a; a += x; }
        s_start[KCLUS] = a;
    }
    __syncthreads();
    if (t < KCLUS) {
        int excl = incl - s_hist[t] + s_wsum[wid];
        s_start[t]  = excl;
        s_cursor[t] = excl;
    }
    __syncthreads();

    // scatter local indices into cluster-contiguous order
    for (int i = t; i < cnt; i += TPB) {
        int pos = atomicAdd(&s_cursor[s_cid[i]], 1);
        s_order[pos] = (unsigned short)i;
    }
    __syncthreads();

    // each warp reduces whole clusters in registers: lane l owns dims 2l,2l+1
    // (warp-uniform s_order index -> uniform-datapath addresses, R8-proven)
    const int lo2 = lane << 1;
    for (int c = wid; c < KCLUS; c += (TPB >> 5)) {
        const int s = s_start[c];
        const int e = s_start[c + 1];
        const int m = e - s;
        if (m == 0) continue;

        float a0 = 0.f, a1 = 0.f, sq = 0.f;
        int j = s;
        // unroll x8: 8 independent 256B row loads in flight per warp (2KB)
        for (; j + 8 <= e; j += 8) {
            float2 v0 = *(const float2*)(X + (((size_t)(base + s_order[j + 0])) << 6) + lo2);
            float2 v1 = *(const float2*)(X + (((size_t)(base + s_order[j + 1])) << 6) + lo2);
            float2 v2 = *(const float2*)(X + (((size_t)(base + s_order[j + 2])) << 6) + lo2);
            float2 v3 = *(const float2*)(X + (((size_t)(base + s_order[j + 3])) << 6) + lo2);
            float2 v4 = *(const float2*)(X + (((size_t)(base + s_order[j + 4])) << 6) + lo2);
            float2 v5 = *(const float2*)(X + (((size_t)(base + s_order[j + 5])) << 6) + lo2);
            float2 v6 = *(const float2*)(X + (((size_t)(base + s_order[j + 6])) << 6) + lo2);
            float2 v7 = *(const float2*)(X + (((size_t)(base + s_order[j + 7])) << 6) + lo2);
            a0 += ((v0.x + v1.x) + (v2.x + v3.x)) + ((v4.x + v5.x) + (v6.x + v7.x));
            a1 += ((v0.y + v1.y) + (v2.y + v3.y)) + ((v4.y + v5.y) + (v6.y + v7.y));
            sq += (v0.x * v0.x + v0.y * v0.y) + (v1.x * v1.x + v1.y * v1.y)
                + (v2.x * v2.x + v2.y * v2.y) + (v3.x * v3.x + v3.y * v3.y)
                + (v4.x * v4.x + v4.y * v4.y) + (v5.x * v5.x + v5.y * v5.y)
                + (v6.x * v6.x + v6.y * v6.y) + (v7.x * v7.x + v7.y * v7.y);
        }
        for (; j < e; j++) {
            float2 v0 = *(const float2*)(X + (((size_t)(base + s_order[j])) << 6) + lo2);
            a0 += v0.x;
            a1 += v0.y;
            sq += v0.x * v0.x + v0.y * v0.y;
        }

        atomicAdd(&g_acc[c * ACCW + lo2 + 0], a0);
        atomicAdd(&g_acc[c * ACCW + lo2 + 1], a1);
        #pragma unroll
        for (int o = 16; o; o >>= 1) sq += __shfl_xor_sync(0xffffffffu, sq, o);
        if (lane == 0) {
            atomicAdd(&g_acc[c * ACCW + 64], sq);
            atomicAdd(&g_acc[c * ACCW + 65], (float)m);
        }
    }
}

// Multi-block epilogue (R8-proven): every block recomputes Ai/Si (26KB L2
// reads, cheap), transposed smem layout [d*K+k] => conflict-free; block i
// reduces its row max over j with 128 threads (<=1 j per thread).
__global__ void dbi_epi(float* out) {
    __shared__ float sA[DFEAT * KCLUS];
    __shared__ float sS[KCLUS];
    __shared__ float wmax[4];
    const int t = threadIdx.x;

    if (t < KCLUS) {
        float nk  = g_acc[t * ACCW + 65];
        float inv = 1.0f / (1.0f + nk);
        float dot = 0.f, nrm = 0.f;
        #pragma unroll
        for (int d = 0; d < DFEAT; d++) {
            float sx = g_acc[t * ACCW + d];
            float a  = (0.001f + sx) * inv;
            sA[d * KCLUS + t] = a;
            dot += a * sx;
            nrm += a * a;
        }
        float ssq = g_acc[t * ACCW + 64] - 2.0f * dot + nk * nrm;
        sS[t] = sqrtf((0.001f + ssq) * inv);
    }
    __syncthreads();

    const int i  = blockIdx.x;
    const float si = sS[i];
    float best = 0.f;
    for (int j = t; j < KCLUS; j += 128) {
        if (j == i) continue;
        float ss = 0.f;
        #pragma unroll
        for (int d = 0; d < DFEAT; d++) {
            float df = sA[d * KCLUS + i] - sA[d * KCLUS + j];
            ss += df * df;
        }
        best = fmaxf(best, (si + sS[j]) / sqrtf(ss));
    }
    #pragma unroll
    for (int o = 16; o; o >>= 1) best = fmaxf(best, __shfl_xor_sync(0xffffffffu, best, o));
    if ((t & 31) == 0) wmax[t >> 5] = best;
    __syncthreads();
    if (t == 0) {
        float b = fmaxf(fmaxf(wmax[0], wmax[1]), fmaxf(wmax[2], wmax[3]));
        atomicAdd(out, b * (1.0f / (float)KCLUS));
    }
}

extern "C" void kernel_launch(void* const* d_in, const int* in_sizes, int n_in,
                              void* d_out, int out_size) {
    const float* X  = (const float*)d_in[0];
    const void*  cl = d_in[1];
    float* out = (float*)d_out;

    int n = (n_in >= 2) ? in_sizes[1] : (in_sizes[0] / DFEAT);

    dbi_init<<<(KCLUS * ACCW + 255) / 256, 256>>>((const int*)cl, n, out);
    dbi_pass1<<<(n + TILE - 1) / TILE, TPB>>>(X, cl, n);
    dbi_epi<<<KCLUS, 128>>>(out);
    (void)out_size;
}

// round 16
// speedup vs baseline: 1.4544x; 1.0547x over previous
#include <cuda_runtime.h>

// Davies-Bouldin index, K=100 clusters, D=64 dims, N=2M fp32 points.
//
// 3 launches (graph-capturable, allocation-free):
//   dbi_init : parallel zero of accumulators + dtype sniff (block 0):
//              JAX x64-off silently makes `clustering` int32.
//   dbi_pass1: streaming pass (R15-proven: TPB=512, 2 CTAs/SM, big tiles).
//              NEW vs R15: balanced grid of exactly 2*148=296 blocks with
//              runtime tile size ceil(n/296) (~6757) -- R15's grid=245 put
//              2 blocks on 97 SMs and 1 on 51, leaving a load-imbalance
//              tail; now every SM carries exactly 2 equal blocks.
//              Per tile: counting-sort by cluster id in smem (warp-parallel
//              scan over 100 bins), then each warp reduces whole clusters
//              in registers (lane l owns dims 2l,2l+1 -> one coalesced
//              256B row per warp-load; warp-uniform s_order index keeps
//              addresses on the uniform datapath), flush 66 floats per
//              (tile,cluster) via global atomicAdd (~2M REDG total).
//   dbi_epi  : multi-block epilogue (proven ~free; single-block variant
//              measured ~40us of one-SM serial smem traffic). Ai/Si from
//              g_acc via sum||x-A||^2 = S2 - 2*A.Sx + n*||A||^2 (no 2nd
//              data pass); block i reduces max_j (Si+Sj)/||Ai-Aj||,
//              atomicAdd /K.

#define KCLUS 100
#define DFEAT 64
#define ACCW  66            // 64 dims + sumsq + count
#define TILEMAX 8192        // smem capacity; runtime tsize <= this
#define TPB   512
#define NSM   148

__device__ float g_acc[KCLUS * ACCW];
__device__ int   g_is64;

// Sniff: view labels as int32 words. int64 (LE, values 0..99) => all odd
// words are 0. int32 => odd-word slots hold uniform cluster ids;
// P(64 samples all zero) ~ 1e-128. Samples stay inside the int32 extent.
__global__ void dbi_init(const int* __restrict__ cl32, int n, float* out) {
    int i = blockIdx.x * blockDim.x + threadIdx.x;
    if (i < KCLUS * ACCW) g_acc[i] = 0.0f;

    if (blockIdx.x == 0) {
        __shared__ int s_flag;
        if (threadIdx.x == 0) s_flag = 0;
        __syncthreads();
        if (threadIdx.x < 64) {
            int step = n / 130;
            if (cl32[2 * (threadIdx.x * step) + 1] != 0) atomicOr(&s_flag, 1);
        }
        __syncthreads();
        if (threadIdx.x == 0) { g_is64 = s_flag ? 0 : 1; out[0] = 0.0f; }
    }
}

__global__ __launch_bounds__(TPB, 2) void dbi_pass1(const float* __restrict__ X,
                                                    const void* __restrict__ cl_raw,
                                                    int n, int tsize) {
    __shared__ unsigned char  s_cid[TILEMAX];
    __shared__ unsigned short s_order[TILEMAX];
    __shared__ int s_hist[KCLUS];
    __shared__ int s_start[KCLUS + 1];
    __shared__ int s_cursor[KCLUS];
    __shared__ int s_wsum[4];

    const int base = blockIdx.x * tsize;
    const int cnt  = min(tsize, n - base);
    if (cnt <= 0) return;              // block-uniform
    const int t    = threadIdx.x;
    const int lane = t & 31;
    const int wid  = t >> 5;

    for (int i = t; i < KCLUS; i += TPB) s_hist[i] = 0;
    __syncthreads();

    // histogram + stash cluster ids (coalesced; uniform dtype branch)
    if (g_is64) {
        const long long* cl = (const long long*)cl_raw;
        for (int i = t; i < cnt; i += TPB) {
            int c = (int)cl[base + i];
            s_cid[i] = (unsigned char)c;
            atomicAdd(&s_hist[c], 1);
        }
    } else {
        const int* cl = (const int*)cl_raw;
        for (int i = t; i < cnt; i += TPB) {
            int c = cl[base + i];
            s_cid[i] = (unsigned char)c;
            atomicAdd(&s_hist[c], 1);
        }
    }
    __syncthreads();

    // warp-parallel exclusive prefix scan over 100 bins (warps 0-3)
    int incl = 0;
    if (t < 128) {
        incl = (t < KCLUS) ? s_hist[t] : 0;
        #pragma unroll
        for (int o = 1; o < 32; o <<= 1) {
            int u = __shfl_up_sync(0xffffffffu, incl, o);
            if (lane >= o) incl += u;
        }
        if (lane == 31) s_wsum[wid] = incl;
    }
    __syncthreads();
    if (t == 0) {
        int a = 0;
        #pragma unroll
        for (int w = 0; w < 4; w++) { int x = s_wsum[w]; s_wsum[w] = a; a += x; }
        s_start[KCLUS] = a;
    }
    __syncthreads();
    if (t < KCLUS) {
        int excl = incl - s_hist[t] + s_wsum[wid];
        s_start[t]  = excl;
        s_cursor[t] = excl;
    }
    __syncthreads();

    // scatter local indices into cluster-contiguous order
    for (int i = t; i < cnt; i += TPB) {
        int pos = atomicAdd(&s_cursor[s_cid[i]], 1);
        s_order[pos] = (unsigned short)i;
    }
    __syncthreads();

    // each warp reduces whole clusters in registers: lane l owns dims 2l,2l+1
    // (warp-uniform s_order index -> uniform-datapath addresses, proven)
    const int lo2 = lane << 1;
    for (int c = wid; c < KCLUS; c += (TPB >> 5)) {
        const int s = s_start[c];
        const int e = s_start[c + 1];
        const int m = e - s;
        if (m == 0) continue;

        float a0 = 0.f, a1 = 0.f, sq = 0.f;
        int j = s;
        // unroll x8: 8 independent 256B row loads in flight per warp (2KB)
        for (; j + 8 <= e; j += 8) {
            float2 v0 = *(const float2*)(X + (((size_t)(base + s_order[j + 0])) << 6) + lo2);
            float2 v1 = *(const float2*)(X + (((size_t)(base + s_order[j + 1])) << 6) + lo2);
            float2 v2 = *(const float2*)(X + (((size_t)(base + s_order[j + 2])) << 6) + lo2);
            float2 v3 = *(const float2*)(X + (((size_t)(base + s_order[j + 3])) << 6) + lo2);
            float2 v4 = *(const float2*)(X + (((size_t)(base + s_order[j + 4])) << 6) + lo2);
            float2 v5 = *(const float2*)(X + (((size_t)(base + s_order[j + 5])) << 6) + lo2);
            float2 v6 = *(const float2*)(X + (((size_t)(base + s_order[j + 6])) << 6) + lo2);
            float2 v7 = *(const float2*)(X + (((size_t)(base + s_order[j + 7])) << 6) + lo2);
            a0 += ((v0.x + v1.x) + (v2.x + v3.x)) + ((v4.x + v5.x) + (v6.x + v7.x));
            a1 += ((v0.y + v1.y) + (v2.y + v3.y)) + ((v4.y + v5.y) + (v6.y + v7.y));
            sq += (v0.x * v0.x + v0.y * v0.y) + (v1.x * v1.x + v1.y * v1.y)
                + (v2.x * v2.x + v2.y * v2.y) + (v3.x * v3.x + v3.y * v3.y)
                + (v4.x * v4.x + v4.y * v4.y) + (v5.x * v5.x + v5.y * v5.y)
                + (v6.x * v6.x + v6.y * v6.y) + (v7.x * v7.x + v7.y * v7.y);
        }
        for (; j < e; j++) {
            float2 v0 = *(const float2*)(X + (((size_t)(base + s_order[j])) << 6) + lo2);
            a0 += v0.x;
            a1 += v0.y;
            sq += v0.x * v0.x + v0.y * v0.y;
        }

        atomicAdd(&g_acc[c * ACCW + lo2 + 0], a0);
        atomicAdd(&g_acc[c * ACCW + lo2 + 1], a1);
        #pragma unroll
        for (int o = 16; o; o >>= 1) sq += __shfl_xor_sync(0xffffffffu, sq, o);
        if (lane == 0) {
            atomicAdd(&g_acc[c * ACCW + 64], sq);
            atomicAdd(&g_acc[c * ACCW + 65], (float)m);
        }
    }
}

// Multi-block epilogue (proven): every block recomputes Ai/Si (26KB L2
// reads, cheap), transposed smem layout [d*K+k] => conflict-free; block i
// reduces its row max over j with 128 threads (<=1 j per thread).
__global__ void dbi_epi(float* out) {
    __shared__ float sA[DFEAT * KCLUS];
    __shared__ float sS[KCLUS];
    __shared__ float wmax[4];
    const int t = threadIdx.x;

    if (t < KCLUS) {
        float nk  = g_acc[t * ACCW + 65];
        float inv = 1.0f / (1.0f + nk);
        float dot = 0.f, nrm = 0.f;
        #pragma unroll
        for (int d = 0; d < DFEAT; d++) {
            float sx = g_acc[t * ACCW + d];
            float a  = (0.001f + sx) * inv;
            sA[d * KCLUS + t] = a;
            dot += a * sx;
            nrm += a * a;
        }
        float ssq = g_acc[t * ACCW + 64] - 2.0f * dot + nk * nrm;
        sS[t] = sqrtf((0.001f + ssq) * inv);
    }
    __syncthreads();

    const int i  = blockIdx.x;
    const float si = sS[i];
    float best = 0.f;
    for (int j = t; j < KCLUS; j += 128) {
        if (j == i) continue;
        float ss = 0.f;
        #pragma unroll
        for (int d = 0; d < DFEAT; d++) {
            float df = sA[d * KCLUS + i] - sA[d * KCLUS + j];
            ss += df * df;
        }
        best = fmaxf(best, (si + sS[j]) / sqrtf(ss));
    }
    #pragma unroll
    for (int o = 16; o; o >>= 1) best = fmaxf(best, __shfl_xor_sync(0xffffffffu, best, o));
    if ((t & 31) == 0) wmax[t >> 5] = best;
    __syncthreads();
    if (t == 0) {
        float b = fmaxf(fmaxf(wmax[0], wmax[1]), fmaxf(wmax[2], wmax[3]));
        atomicAdd(out, b * (1.0f / (float)KCLUS));
    }
}

extern "C" void kernel_launch(void* const* d_in, const int* in_sizes, int n_in,
                              void* d_out, int out_size) {
    const float* X  = (const float*)d_in[0];
    const void*  cl = d_in[1];
    float* out = (float*)d_out;

    int n = (n_in >= 2) ? in_sizes[1] : (in_sizes[0] / DFEAT);

    // balanced: exactly 2 blocks per SM, equal runtime tile size
    int grid  = 2 * NSM;
    int tsize = (n + grid - 1) / grid;
    if (tsize > TILEMAX) {             // fallback for larger n
        tsize = TILEMAX;
        grid  = (n + tsize - 1) / tsize;
    }

    dbi_init<<<(KCLUS * ACCW + 255) / 256, 256>>>((const int*)cl, n, out);
    dbi_pass1<<<grid, TPB>>>(X, cl, n, tsize);
    dbi_epi<<<KCLUS, 128>>>(out);
    (void)out_size;
}